// round 2
// baseline (speedup 1.0000x reference)
#include <cuda_runtime.h>

#define BATCH     16384
#define QSEQ      1204
#define FDIM      7
#define NQUAD     301
#define NCHUNKS   120
#define NOFF      5
#define WINSZ     10
#define NCAT      600
#define H1DIM     128
#define H2DIM     32
#define ODIM      2

// Scratch: cat stored k-major: cat_g[k*BATCH + b]
__device__ float g_cat[(size_t)NCAT * BATCH];

// ---------------------------------------------------------------------------
// f32x2 packed helpers (Blackwell FFMA2 — only reachable via PTX fma.rn.f32x2)
// ---------------------------------------------------------------------------
__device__ __forceinline__ unsigned long long pack2(float lo, float hi) {
    unsigned long long r;
    asm("mov.b64 %0, {%1, %2};" : "=l"(r) : "f"(lo), "f"(hi));
    return r;
}
__device__ __forceinline__ void unpack2(unsigned long long v, float& lo, float& hi) {
    asm("mov.b64 {%0, %1}, %2;" : "=f"(lo), "=f"(hi) : "l"(v));
}
__device__ __forceinline__ unsigned long long ffma2(unsigned long long a,
                                                    unsigned long long b,
                                                    unsigned long long c) {
    unsigned long long d;
    asm("fma.rn.f32x2 %0, %1, %2, %3;" : "=l"(d) : "l"(a), "l"(b), "l"(c));
    return d;
}

// ===========================================================================
// Kernel 1: dot-7 + windowed max pool  (DRAM-streaming)
//   8 rows per CTA, 256 threads, one barrier. Writes g_cat[k*BATCH + b].
// ===========================================================================
#define K1_ROWS 8
__global__ __launch_bounds__(256)
void pool_kernel(const float* __restrict__ x,
                 const float* __restrict__ w_step,
                 const float* __restrict__ b_step)
{
    __shared__ float sm_out[K1_ROWS][QSEQ];

    const int tid = threadIdx.x;
    const size_t b0 = (size_t)blockIdx.x * K1_ROWS;

    float ws[FDIM];
#pragma unroll
    for (int f = 0; f < FDIM; ++f) ws[f] = __ldg(&w_step[f]);
    const float bs = __ldg(b_step);

    // ---- Stage A: dots for all 8 rows in parallel (2408 quad-items) ----
    for (int it = tid; it < K1_ROWS * NQUAD; it += 256) {
        const int r  = it / NQUAD;
        const int qd = it - r * NQUAD;
        const float4* p = (const float4*)(x + (b0 + (size_t)r) * (QSEQ * FDIM) + qd * 28);
        float v[28];
#pragma unroll
        for (int i = 0; i < 7; ++i) {
            float4 t = p[i];
            v[i*4+0] = t.x; v[i*4+1] = t.y; v[i*4+2] = t.z; v[i*4+3] = t.w;
        }
#pragma unroll
        for (int qq = 0; qq < 4; ++qq) {
            float acc = bs;
#pragma unroll
            for (int f = 0; f < FDIM; ++f)
                acc = fmaf(v[qq*FDIM + f], ws[f], acc);
            sm_out[r][qd*4 + qq] = acc;
        }
    }
    __syncthreads();

    // ---- Stage B: pooling. Item = (row, chunk i), produces 5 offsets. ----
    // window [s, s+10), s = i*10+o, o in 0..4 -> needs v[i*10 .. i*10+14)
    // All windows contain [i*10+4, i*10+10) (the "common" span).
    for (int it = tid; it < K1_ROWS * NCHUNKS; it += 256) {
        const int r = it & (K1_ROWS - 1);
        const int i = it >> 3;
        const float* o = &sm_out[r][i * WINSZ];
        float v[14];
#pragma unroll
        for (int j = 0; j < 14; ++j) v[j] = o[j];

        float common = v[4];
#pragma unroll
        for (int j = 5; j < 10; ++j) common = fmaxf(common, v[j]);
        // prefix maxes of v[10..13]
        const float P1 = v[10];
        const float P2 = fmaxf(P1, v[11]);
        const float P3 = fmaxf(P2, v[12]);
        const float P4 = fmaxf(P3, v[13]);
        // suffix maxes of v[0..3]
        const float T3 = v[3];
        const float T2 = fmaxf(v[2], T3);
        const float T1 = fmaxf(v[1], T2);
        const float T0 = fmaxf(v[0], T1);

        const float m0 = fmaxf(common, T0);
        const float m1 = fmaxf(fmaxf(common, T1), P1);
        const float m2 = fmaxf(fmaxf(common, T2), P2);
        const float m3 = fmaxf(fmaxf(common, T3), P3);
        const float m4 = fmaxf(common, P4);

        const size_t base = b0 + (size_t)r;
        const size_t c0 = (size_t)(i * NOFF) * BATCH;
        g_cat[c0 + 0*BATCH + base] = m0;
        g_cat[c0 + 1*BATCH + base] = m1;
        g_cat[c0 + 2*BATCH + base] = m2;
        g_cat[c0 + 3*BATCH + base] = m3;
        g_cat[c0 + 4*BATCH + base] = m4;
    }
}

// ===========================================================================
// Kernel 2: 3-layer MLP.  16 rows/CTA, 256 threads, FFMA2 layer A.
// ===========================================================================
#define K2_ROWS 16
__global__ __launch_bounds__(256)
void mlp_kernel(const float* __restrict__ wA,
                const float* __restrict__ bA,
                const float* __restrict__ wB,
                const float* __restrict__ bB,
                const float* __restrict__ wC,
                const float* __restrict__ bC,
                float* __restrict__ out)
{
    // sm_cat [k][16] : 9600 floats; h1 aliases sm_cat after stage 2; h2 after.
    __shared__ float smem[NCAT * K2_ROWS + K2_ROWS * H2DIM];
    float* sm_cat = smem;                 // 9600
    float* sm_h1  = smem;                 // 2048 (alias, used after sync)
    float* sm_h2  = smem + NCAT * K2_ROWS; // 512

    const int tid = threadIdx.x;
    const size_t b0 = (size_t)blockIdx.x * K2_ROWS;

    // ---- load cat tile (2400 float4) ----
    for (int idx = tid; idx < NCAT * K2_ROWS / 4; idx += 256) {
        const int k  = idx >> 2;
        const int r4 = idx & 3;
        float4 t = *(const float4*)&g_cat[(size_t)k * BATCH + b0 + r4 * 4];
        *(float4*)&sm_cat[k * K2_ROWS + r4 * 4] = t;
    }
    __syncthreads();

    // ---- Layer A: h1 = relu(cat @ wA + bA), packed f32x2 ----
    // thread: neuron j = tid&127, rows r0..r0+7 as 4 packed pairs
    {
        const int j  = tid & (H1DIM - 1);
        const int r0 = (tid >> 7) * 8;
        unsigned long long acc0 = 0ULL, acc1 = 0ULL, acc2 = 0ULL, acc3 = 0ULL;
        const float* wAj = wA + j;
#pragma unroll 4
        for (int k = 0; k < NCAT; ++k) {
            const float wa = __ldg(&wAj[k * H1DIM]);
            const unsigned long long wv = pack2(wa, wa);
            const ulonglong2 u0 = *(const ulonglong2*)&sm_cat[k * K2_ROWS + r0];
            const ulonglong2 u1 = *(const ulonglong2*)&sm_cat[k * K2_ROWS + r0 + 4];
            acc0 = ffma2(u0.x, wv, acc0);
            acc1 = ffma2(u0.y, wv, acc1);
            acc2 = ffma2(u1.x, wv, acc2);
            acc3 = ffma2(u1.y, wv, acc3);
        }
        const float bj = __ldg(&bA[j]);
        __syncthreads();   // all sm_cat reads done; safe to overwrite with h1
        float a, b;
        unpack2(acc0, a, b);
        sm_h1[j * K2_ROWS + r0 + 0] = fmaxf(a + bj, 0.0f);
        sm_h1[j * K2_ROWS + r0 + 1] = fmaxf(b + bj, 0.0f);
        unpack2(acc1, a, b);
        sm_h1[j * K2_ROWS + r0 + 2] = fmaxf(a + bj, 0.0f);
        sm_h1[j * K2_ROWS + r0 + 3] = fmaxf(b + bj, 0.0f);
        unpack2(acc2, a, b);
        sm_h1[j * K2_ROWS + r0 + 4] = fmaxf(a + bj, 0.0f);
        sm_h1[j * K2_ROWS + r0 + 5] = fmaxf(b + bj, 0.0f);
        unpack2(acc3, a, b);
        sm_h1[j * K2_ROWS + r0 + 6] = fmaxf(a + bj, 0.0f);
        sm_h1[j * K2_ROWS + r0 + 7] = fmaxf(b + bj, 0.0f);
    }
    __syncthreads();

    // ---- Layer B: h2 = relu(h1 @ wB + bB) ----
    {
        const int m  = tid & (H2DIM - 1);
        const int rp = tid >> 5;                 // 0..7 -> rows 2rp, 2rp+1
        float a0 = 0.0f, a1 = 0.0f;
        const float* wBm = wB + m;
#pragma unroll 4
        for (int j = 0; j < H1DIM; ++j) {
            const float wb = __ldg(&wBm[j * H2DIM]);
            const float2 h = *(const float2*)&sm_h1[j * K2_ROWS + rp * 2];
            a0 = fmaf(h.x, wb, a0);
            a1 = fmaf(h.y, wb, a1);
        }
        const float bm = __ldg(&bB[m]);
        sm_h2[(rp * 2 + 0) * H2DIM + m] = fmaxf(a0 + bm, 0.0f);
        sm_h2[(rp * 2 + 1) * H2DIM + m] = fmaxf(a1 + bm, 0.0f);
    }
    __syncthreads();

    // ---- Layer C: out = h2 @ wC + bC ----
    if (tid < K2_ROWS * ODIM) {
        const int r = tid >> 1;
        const int c = tid & 1;
        float acc = __ldg(&bC[c]);
#pragma unroll
        for (int m = 0; m < H2DIM; ++m)
            acc = fmaf(sm_h2[r * H2DIM + m], __ldg(&wC[m * ODIM + c]), acc);
        out[(b0 + (size_t)r) * ODIM + c] = acc;
    }
}

extern "C" void kernel_launch(void* const* d_in, const int* in_sizes, int n_in,
                              void* d_out, int out_size)
{
    const float* x      = (const float*)d_in[0];
    const float* w_step = (const float*)d_in[1];
    const float* b_step = (const float*)d_in[2];
    const float* wA     = (const float*)d_in[3];
    const float* bA     = (const float*)d_in[4];
    const float* wB     = (const float*)d_in[5];
    const float* bB     = (const float*)d_in[6];
    const float* wC     = (const float*)d_in[7];
    const float* bC     = (const float*)d_in[8];
    float* out          = (float*)d_out;

    pool_kernel<<<BATCH / K1_ROWS, 256>>>(x, w_step, b_step);
    mlp_kernel<<<BATCH / K2_ROWS, 256>>>(wA, bA, wB, bB, wC, bC, out);
}

// round 3
// speedup vs baseline: 1.0575x; 1.0575x over previous
#include <cuda_runtime.h>

#define BATCH     16384
#define QSEQ      1204
#define FDIM      7
#define NQUAD     301
#define NCHUNKS   120
#define NOFF      5
#define WINSZ     10
#define NCAT      600
#define H1DIM     128
#define H2DIM     32
#define ODIM      2

// Scratch: cat stored k-major: g_cat[k*BATCH + b]
__device__ float g_cat[(size_t)NCAT * BATCH];

// ---------------------------------------------------------------------------
// f32x2 packed FFMA helpers
// ---------------------------------------------------------------------------
__device__ __forceinline__ unsigned long long pack2(float lo, float hi) {
    unsigned long long r;
    asm("mov.b64 %0, {%1, %2};" : "=l"(r) : "f"(lo), "f"(hi));
    return r;
}
__device__ __forceinline__ void unpack2(unsigned long long v, float& lo, float& hi) {
    asm("mov.b64 {%0, %1}, %2;" : "=f"(lo), "=f"(hi) : "l"(v));
}
__device__ __forceinline__ unsigned long long ffma2(unsigned long long a,
                                                    unsigned long long b,
                                                    unsigned long long c) {
    unsigned long long d;
    asm("fma.rn.f32x2 %0, %1, %2, %3;" : "=l"(d) : "l"(a), "l"(b), "l"(c));
    return d;
}

// ---------------------------------------------------------------------------
// cp.async helpers
// ---------------------------------------------------------------------------
__device__ __forceinline__ void cp_async16(void* smem_dst, const void* gsrc) {
    unsigned s = (unsigned)__cvta_generic_to_shared(smem_dst);
    asm volatile("cp.async.ca.shared.global [%0], [%1], 16;\n" :: "r"(s), "l"(gsrc));
}
__device__ __forceinline__ void cp_commit() {
    asm volatile("cp.async.commit_group;\n" ::: "memory");
}
__device__ __forceinline__ void cp_wait1() {
    asm volatile("cp.async.wait_group 1;\n" ::: "memory");
}
__device__ __forceinline__ void cp_wait0() {
    asm volatile("cp.async.wait_group 0;\n" ::: "memory");
}

// ===========================================================================
// Kernel 1: dot-7 + windowed max pool (DRAM streaming)
// ===========================================================================
#define K1_ROWS 8
__global__ __launch_bounds__(256)
void pool_kernel(const float* __restrict__ x,
                 const float* __restrict__ w_step,
                 const float* __restrict__ b_step)
{
    __shared__ float sm_out[K1_ROWS][QSEQ];

    const int tid = threadIdx.x;
    const size_t b0 = (size_t)blockIdx.x * K1_ROWS;

    float ws[FDIM];
#pragma unroll
    for (int f = 0; f < FDIM; ++f) ws[f] = __ldg(&w_step[f]);
    const float bs = __ldg(b_step);

    // ---- Stage A: dots for all 8 rows in parallel ----
    for (int it = tid; it < K1_ROWS * NQUAD; it += 256) {
        const int r  = it / NQUAD;
        const int qd = it - r * NQUAD;
        const float4* p = (const float4*)(x + (b0 + (size_t)r) * (QSEQ * FDIM) + qd * 28);
        float v[28];
#pragma unroll
        for (int i = 0; i < 7; ++i) {
            float4 t = p[i];
            v[i*4+0] = t.x; v[i*4+1] = t.y; v[i*4+2] = t.z; v[i*4+3] = t.w;
        }
#pragma unroll
        for (int qq = 0; qq < 4; ++qq) {
            float acc = bs;
#pragma unroll
            for (int f = 0; f < FDIM; ++f)
                acc = fmaf(v[qq*FDIM + f], ws[f], acc);
            sm_out[r][qd*4 + qq] = acc;
        }
    }
    __syncthreads();

    // ---- Stage B: windowed max via common/prefix/suffix decomposition ----
    for (int it = tid; it < K1_ROWS * NCHUNKS; it += 256) {
        const int r = it & (K1_ROWS - 1);
        const int i = it >> 3;
        const float* o = &sm_out[r][i * WINSZ];
        float v[14];
#pragma unroll
        for (int j = 0; j < 14; ++j) v[j] = o[j];

        float common = v[4];
#pragma unroll
        for (int j = 5; j < 10; ++j) common = fmaxf(common, v[j]);
        const float P1 = v[10];
        const float P2 = fmaxf(P1, v[11]);
        const float P3 = fmaxf(P2, v[12]);
        const float P4 = fmaxf(P3, v[13]);
        const float T3 = v[3];
        const float T2 = fmaxf(v[2], T3);
        const float T1 = fmaxf(v[1], T2);
        const float T0 = fmaxf(v[0], T1);

        const size_t base = b0 + (size_t)r;
        const size_t c0 = (size_t)(i * NOFF) * BATCH;
        g_cat[c0 + 0*BATCH + base] = fmaxf(common, T0);
        g_cat[c0 + 1*BATCH + base] = fmaxf(fmaxf(common, T1), P1);
        g_cat[c0 + 2*BATCH + base] = fmaxf(fmaxf(common, T2), P2);
        g_cat[c0 + 3*BATCH + base] = fmaxf(fmaxf(common, T3), P3);
        g_cat[c0 + 4*BATCH + base] = fmaxf(common, P4);
    }
}

// ===========================================================================
// Kernel 2: MLP with cp.async double-buffered wA k-tiles in shared memory
// ===========================================================================
#define K2_ROWS 16
#define KT      60          // k-tile size (600 = 10 * 60)
#define NTILE   10
#define TILE_F  (KT * H1DIM)              // 7680 floats per tile buffer

// dynamic smem layout (floats):
//   sm_cat : [0, 9600)          cat tile [k][16]   (aliased by h1 after layer A)
//   sm_wA0 : [9600, 17280)
//   sm_wA1 : [17280, 24960)
//   sm_h2  : [24960, 25472)
#define SM_TOTAL_F 25472
#define SM_BYTES   (SM_TOTAL_F * 4)

__global__ __launch_bounds__(256)
void mlp_kernel(const float* __restrict__ wA,
                const float* __restrict__ bA,
                const float* __restrict__ wB,
                const float* __restrict__ bB,
                const float* __restrict__ wC,
                const float* __restrict__ bC,
                float* __restrict__ out)
{
    extern __shared__ float smem[];
    float* sm_cat = smem;                     // 9600
    float* sm_h1  = smem;                     // alias (2048) after layer A
    float* sm_wAb[2] = { smem + 9600, smem + 17280 };
    float* sm_h2  = smem + 24960;             // 512

    const int tid = threadIdx.x;
    const size_t b0 = (size_t)blockIdx.x * K2_ROWS;

    // ---- group 0: wA tile 0 + cat tile, all via cp.async ----
    {
        const float* src = wA;                // tile 0 is contiguous
        for (int i = tid; i < TILE_F / 4; i += 256)
            cp_async16(sm_wAb[0] + i * 4, src + i * 4);
        for (int idx = tid; idx < NCAT * K2_ROWS / 4; idx += 256) {
            const int k  = idx >> 2;
            const int r4 = idx & 3;
            cp_async16(&sm_cat[k * K2_ROWS + r4 * 4],
                       &g_cat[(size_t)k * BATCH + b0 + r4 * 4]);
        }
        cp_commit();
    }

    // ---- Layer A over k-tiles, double buffered ----
    const int j  = tid & (H1DIM - 1);
    const int r0 = (tid >> 7) * 8;
    unsigned long long acc0 = 0ULL, acc1 = 0ULL, acc2 = 0ULL, acc3 = 0ULL;

    for (int t = 0; t < NTILE; ++t) {
        if (t + 1 < NTILE) {
            const float* src = wA + (size_t)(t + 1) * TILE_F;
            float* dst = sm_wAb[(t + 1) & 1];
            for (int i = tid; i < TILE_F / 4; i += 256)
                cp_async16(dst + i * 4, src + i * 4);
            cp_commit();
            cp_wait1();          // tile t (and cat, if t==0) has landed
        } else {
            cp_wait0();
        }
        __syncthreads();

        const float* wt = sm_wAb[t & 1];
        const float* cb = sm_cat + t * KT * K2_ROWS;
#pragma unroll 4
        for (int kk = 0; kk < KT; ++kk) {
            const float wa = wt[kk * H1DIM + j];
            const unsigned long long wv = pack2(wa, wa);
            const ulonglong2 u0 = *(const ulonglong2*)&cb[kk * K2_ROWS + r0];
            const ulonglong2 u1 = *(const ulonglong2*)&cb[kk * K2_ROWS + r0 + 4];
            acc0 = ffma2(u0.x, wv, acc0);
            acc1 = ffma2(u0.y, wv, acc1);
            acc2 = ffma2(u1.x, wv, acc2);
            acc3 = ffma2(u1.y, wv, acc3);
        }
        __syncthreads();          // all reads of this buffer done before refill
    }

    // ---- bias + relu, write h1 (aliases sm_cat; all cat reads are done) ----
    {
        const float bj = __ldg(&bA[j]);
        float a, b;
        unpack2(acc0, a, b);
        sm_h1[j * K2_ROWS + r0 + 0] = fmaxf(a + bj, 0.0f);
        sm_h1[j * K2_ROWS + r0 + 1] = fmaxf(b + bj, 0.0f);
        unpack2(acc1, a, b);
        sm_h1[j * K2_ROWS + r0 + 2] = fmaxf(a + bj, 0.0f);
        sm_h1[j * K2_ROWS + r0 + 3] = fmaxf(b + bj, 0.0f);
        unpack2(acc2, a, b);
        sm_h1[j * K2_ROWS + r0 + 4] = fmaxf(a + bj, 0.0f);
        sm_h1[j * K2_ROWS + r0 + 5] = fmaxf(b + bj, 0.0f);
        unpack2(acc3, a, b);
        sm_h1[j * K2_ROWS + r0 + 6] = fmaxf(a + bj, 0.0f);
        sm_h1[j * K2_ROWS + r0 + 7] = fmaxf(b + bj, 0.0f);
    }
    __syncthreads();

    // ---- Layer B: h2 = relu(h1 @ wB + bB) ----
    {
        const int m  = tid & (H2DIM - 1);
        const int rp = tid >> 5;
        float a0 = 0.0f, a1 = 0.0f;
        const float* wBm = wB + m;
#pragma unroll 4
        for (int jj = 0; jj < H1DIM; ++jj) {
            const float wb = __ldg(&wBm[jj * H2DIM]);
            const float2 h = *(const float2*)&sm_h1[jj * K2_ROWS + rp * 2];
            a0 = fmaf(h.x, wb, a0);
            a1 = fmaf(h.y, wb, a1);
        }
        const float bm = __ldg(&bB[m]);
        sm_h2[(rp * 2 + 0) * H2DIM + m] = fmaxf(a0 + bm, 0.0f);
        sm_h2[(rp * 2 + 1) * H2DIM + m] = fmaxf(a1 + bm, 0.0f);
    }
    __syncthreads();

    // ---- Layer C: out = h2 @ wC + bC ----
    if (tid < K2_ROWS * ODIM) {
        const int r = tid >> 1;
        const int c = tid & 1;
        float acc = __ldg(&bC[c]);
#pragma unroll
        for (int m = 0; m < H2DIM; ++m)
            acc = fmaf(sm_h2[r * H2DIM + m], __ldg(&wC[m * ODIM + c]), acc);
        out[(b0 + (size_t)r) * ODIM + c] = acc;
    }
}

extern "C" void kernel_launch(void* const* d_in, const int* in_sizes, int n_in,
                              void* d_out, int out_size)
{
    const float* x      = (const float*)d_in[0];
    const float* w_step = (const float*)d_in[1];
    const float* b_step = (const float*)d_in[2];
    const float* wA     = (const float*)d_in[3];
    const float* bA     = (const float*)d_in[4];
    const float* wB     = (const float*)d_in[5];
    const float* bB     = (const float*)d_in[6];
    const float* wC     = (const float*)d_in[7];
    const float* bC     = (const float*)d_in[8];
    float* out          = (float*)d_out;

    cudaFuncSetAttribute(mlp_kernel, cudaFuncAttributeMaxDynamicSharedMemorySize, SM_BYTES);

    pool_kernel<<<BATCH / K1_ROWS, 256>>>(x, w_step, b_step);
    mlp_kernel<<<BATCH / K2_ROWS, 256, SM_BYTES>>>(wA, bA, wB, bB, wC, bC, out);
}